// round 11
// baseline (speedup 1.0000x reference)
#include <cuda_runtime.h>
#include <math.h>
#include <cstdint>

#define BSZ  16      // batch
#define NCAP 1152    // primary caps
#define DP   8       // dim primary
#define DDIG 10      // digit caps
#define DD   16      // dim digit

#define TILE_N 16
#define NT (NCAP / TILE_N)   // 72

#define K2TN 2               // n per k2 CTA
#define K2CTAS (NCAP / K2TN) // 576

// Scratch (device globals; zero-init at load; invariants restored every call)
__device__ __align__(16) float g_T[BSZ * DDIG * DD];   // T (k1 atomics; re-zeroed)
__device__ __align__(16) float g_S[BSZ * DDIG * DD];   // S (k2 atomics; re-zeroed)
__device__ unsigned int g_cnt;                          // self-resetting wrap counter

// -------------------------------------------------------------------------
// K1: T[b,d,j] = sum_n W[d,n,j,:]·u[b,n,:]   (no U_hat materialization)
// Grid (DDIG, NT) = 720 CTAs x 256 threads.   (proven R10)
// -------------------------------------------------------------------------
__global__ __launch_bounds__(256) void k1_votes(
    const float* __restrict__ u,   // [B][N][DP]
    const float* __restrict__ W)   // [D][N][DD][DP]
{
    const int d    = blockIdx.x;
    const int tile = blockIdx.y;
    const int n0   = tile * TILE_N;
    const int t    = threadIdx.x;
    const int j    = t & 15;
    const int nl   = t >> 4;
    const int n    = n0 + nl;
    const int lane = t & 31;
    const int w    = t >> 5;

    const float4* wp = reinterpret_cast<const float4*>(
        W + ((size_t)(d * NCAP + n) * DD + j) * DP);
    const float4 w0 = wp[0];
    const float4 w1 = wp[1];

    __shared__ __align__(16) float us[BSZ][TILE_N][DP];   // 8 KB
    __shared__ float red[BSZ][8][DD];                     // 8 KB

    #pragma unroll
    for (int it = 0; it < 2; ++it) {
        const int idx = it * 256 + t;
        const int b   = idx >> 5;
        const int rem = idx & 31;
        const float4 v = reinterpret_cast<const float4*>(
            u + (size_t)b * NCAP * DP + (size_t)n0 * DP)[rem];
        reinterpret_cast<float4*>(&us[b][0][0])[rem] = v;
    }
    __syncthreads();

    #pragma unroll
    for (int b = 0; b < BSZ; ++b) {
        const float4* up = reinterpret_cast<const float4*>(&us[b][nl][0]);
        const float4 u0 = up[0];
        const float4 u1 = up[1];
        const float acc = w0.x * u0.x + w0.y * u0.y + w0.z * u0.z + w0.w * u0.w
                        + w1.x * u1.x + w1.y * u1.y + w1.z * u1.z + w1.w * u1.w;
        const float ps = acc + __shfl_xor_sync(0xffffffffu, acc, 16);
        if (lane < 16) red[b][w][lane] = ps;
    }
    __syncthreads();

    {
        const int b2 = t >> 4;
        const int j2 = t & 15;
        float s = 0.f;
        #pragma unroll
        for (int ww = 0; ww < 8; ++ww) s += red[b2][ww][j2];
        atomicAdd(&g_T[(b2 * DDIG + d) * DD + j2], s);
    }
}

// -------------------------------------------------------------------------
// K2: recompute pass, reg-resident W. Grid 576 CTAs x 160 threads.
// thread t = d*16 + j. W rows (2 n) and T (16 b) in registers; u broadcast
// from SMEM. Pass1: uh per (nl,b) -> a via xor16 shfl. Softmax (32 thr).
// Pass2: uh recomputed from reg-W, Sacc[16b] in regs, coalesced REDs.
// Last CTA (fence + wrap counter) squashes all b and resets g_S/g_T.
// -------------------------------------------------------------------------
__global__ __launch_bounds__(160) void k2_rest(
    const float* __restrict__ u,   // [B][N][DP]
    const float* __restrict__ W,   // [D][N][DD][DP]
    const float* __restrict__ Bp,  // [D][1][N]
    float* __restrict__ out)       // [B][D][DD]
{
    const int n0 = blockIdx.x * K2TN;
    const int t  = threadIdx.x;      // 0..159
    const int d  = t >> 4;           // 0..9
    const int j  = t & 15;

    __shared__ __align__(16) float us[BSZ][K2TN][DP];   // 1 KB
    __shared__ float a_s[BSZ][K2TN][DDIG];              // 1.25 KB
    __shared__ float wgt_s[BSZ][K2TN][DDIG];            // 1.25 KB
    __shared__ float Bp_s[K2TN][DDIG];
    __shared__ __align__(16) float Ssm[BSZ * DDIG * DD]; // 10 KB (finalize only)
    __shared__ float coef[BSZ * DDIG];
    __shared__ unsigned int is_last;

    // ---- issue W (4 f4) and T (16 scalar, coalesced) loads up front ----
    float4 wr[K2TN][2];
    #pragma unroll
    for (int nl = 0; nl < K2TN; ++nl) {
        const float4* wp = reinterpret_cast<const float4*>(
            W + ((size_t)(d * NCAP + n0 + nl) * DD + j) * DP);
        wr[nl][0] = wp[0];
        wr[nl][1] = wp[1];
    }
    float Treg[BSZ];
    #pragma unroll
    for (int b = 0; b < BSZ; ++b)
        Treg[b] = g_T[(b * DDIG + d) * DD + j];

    // ---- stage u (64 threads x f4) and Bp tile ----
    if (t < 64) {
        const int b = t >> 2;
        const int q = t & 3;
        reinterpret_cast<float4*>(&us[0][0][0])[t] =
            reinterpret_cast<const float4*>(u)[
                (size_t)b * (NCAP * DP / 4) + (size_t)n0 * (DP / 4) + q];
    }
    if (t < K2TN * DDIG) {
        const int dd = t / K2TN;
        const int nl = t % K2TN;
        Bp_s[nl][dd] = Bp[(size_t)dd * NCAP + n0 + nl];
    }
    __syncthreads();

    const float inv_sqrt8 = 0.3535533905932738f;

    // ---- pass 1: a[b,d,n] via in-warp j reduction ----
    #pragma unroll
    for (int nl = 0; nl < K2TN; ++nl) {
        #pragma unroll
        for (int b = 0; b < BSZ; ++b) {
            const float4* up = reinterpret_cast<const float4*>(&us[b][nl][0]);
            const float4 u0 = up[0];
            const float4 u1 = up[1];
            const float uh =
                  wr[nl][0].x * u0.x + wr[nl][0].y * u0.y
                + wr[nl][0].z * u0.z + wr[nl][0].w * u0.w
                + wr[nl][1].x * u1.x + wr[nl][1].y * u1.y
                + wr[nl][1].z * u1.z + wr[nl][1].w * u1.w;
            float p = Treg[b] * uh;
            p += __shfl_xor_sync(0xffffffffu, p, 1);
            p += __shfl_xor_sync(0xffffffffu, p, 2);
            p += __shfl_xor_sync(0xffffffffu, p, 4);
            p += __shfl_xor_sync(0xffffffffu, p, 8);
            if (j == 0) a_s[b][nl][d] = p * inv_sqrt8;
        }
    }
    __syncthreads();

    // ---- softmax over d (32 threads: one per (b,nl)) ----
    if (t < BSZ * K2TN) {
        const int b  = t & 15;
        const int nl = t >> 4;
        float a[DDIG];
        #pragma unroll
        for (int dd = 0; dd < DDIG; ++dd) a[dd] = a_s[b][nl][dd];
        float m = a[0];
        #pragma unroll
        for (int dd = 1; dd < DDIG; ++dd) m = fmaxf(m, a[dd]);
        float denom = 0.f;
        #pragma unroll
        for (int dd = 0; dd < DDIG; ++dd) { a[dd] = __expf(a[dd] - m); denom += a[dd]; }
        const float rden = 1.f / denom;
        #pragma unroll
        for (int dd = 0; dd < DDIG; ++dd)
            wgt_s[b][nl][dd] = a[dd] * rden + Bp_s[nl][dd];
    }
    __syncthreads();

    // ---- pass 2: S accumulation (uh recomputed from reg-W) ----
    float Sacc[BSZ];
    #pragma unroll
    for (int b = 0; b < BSZ; ++b) Sacc[b] = 0.f;

    #pragma unroll
    for (int nl = 0; nl < K2TN; ++nl) {
        #pragma unroll
        for (int b = 0; b < BSZ; ++b) {
            const float4* up = reinterpret_cast<const float4*>(&us[b][nl][0]);
            const float4 u0 = up[0];
            const float4 u1 = up[1];
            const float uh =
                  wr[nl][0].x * u0.x + wr[nl][0].y * u0.y
                + wr[nl][0].z * u0.z + wr[nl][0].w * u0.w
                + wr[nl][1].x * u1.x + wr[nl][1].y * u1.y
                + wr[nl][1].z * u1.z + wr[nl][1].w * u1.w;
            Sacc[b] += wgt_s[b][nl][d] * uh;
        }
    }

    // coalesced spread-address REDs: per b, 32 lanes hit consecutive floats
    #pragma unroll
    for (int b = 0; b < BSZ; ++b)
        atomicAdd(&g_S[(b * DDIG + d) * DD + j], Sacc[b]);

    // ---- last-CTA finalize ----
    __threadfence();
    __syncthreads();
    if (t == 0)
        is_last = (atomicInc(&g_cnt, K2CTAS - 1) == K2CTAS - 1) ? 1u : 0u;
    __syncthreads();
    if (!is_last) return;

    for (int idx = t; idx < BSZ * DDIG * DD; idx += 160) {
        Ssm[idx] = __ldcg(&g_S[idx]);   // L2-fresh
        g_S[idx] = 0.f;                 // restore invariants for next call
        g_T[idx] = 0.f;
    }
    __syncthreads();
    if (t < BSZ * DDIG) {               // t = b*10+d
        float nn = 0.f;
        #pragma unroll
        for (int jj = 0; jj < DD; ++jj) {
            const float v = Ssm[t * DD + jj];
            nn += v * v;
        }
        const float norm = sqrtf(nn);
        const float EPS  = 1e-7f;
        coef[t] = (1.f - 1.f / (__expf(norm) + EPS)) / (norm + EPS);
    }
    __syncthreads();
    for (int idx = t; idx < BSZ * DDIG * DD; idx += 160)
        out[idx] = coef[idx >> 4] * Ssm[idx];
}

// -------------------------------------------------------------------------
extern "C" void kernel_launch(void* const* d_in, const int* in_sizes, int n_in,
                              void* d_out, int out_size)
{
    const float* u  = (const float*)d_in[0];   // primary_caps [16,1152,8]
    const float* W  = (const float*)d_in[1];   // W            [10,1152,16,8]
    const float* Bp = (const float*)d_in[2];   // B_prior      [10,1,1152]
    float* out      = (float*)d_out;           // [16,10,16]

    (void)in_sizes; (void)n_in; (void)out_size;

    k1_votes<<<dim3(DDIG, NT), 256>>>(u, W);
    k2_rest <<<K2CTAS, 160>>>(u, W, Bp, out);
}

// round 12
// speedup vs baseline: 1.0736x; 1.0736x over previous
#include <cuda_runtime.h>
#include <math.h>
#include <cstdint>

#define BSZ  16      // batch
#define NCAP 1152    // primary caps
#define DP   8       // dim primary
#define DDIG 10      // digit caps
#define DD   16      // dim digit

#define TILE_N 16
#define NT (NCAP / TILE_N)   // 72
#define TSTRIPE 4            // stripes for T atomics

#define K2CH 9               // k2 chunks per b
#define K2N (NCAP / K2CH)    // 128

#define K3H 2                // n-halves in k3
#define K3N (NCAP / K3H)     // 576
#define K3CTAS (BSZ * DDIG * K3H)   // 320

// Scratch (device globals; zero-init at load; invariants restored every call)
__device__ __align__(16) float g_U  [BSZ * DDIG * NCAP * DD];       // U_hat
__device__ __align__(16) float g_T4 [TSTRIPE][BSZ * DDIG * DD];     // striped T atomics
__device__ __align__(16) float g_wgt[BSZ * DDIG * NCAP];            // weights [b][d][n]
__device__ __align__(16) float g_Sp [K3H][BSZ * DDIG * DD];         // S partials
__device__ unsigned int g_cnt;                                      // wrap counter

// -------------------------------------------------------------------------
// K1: votes U_hat[b,d,n,j] = W[d,n,j,:]·u[b,n,:]; T via 4-way striped atomics
// Grid (DDIG, NT) = 720 CTAs x 256 threads.
// -------------------------------------------------------------------------
__global__ __launch_bounds__(256) void k1_votes(
    const float* __restrict__ u,   // [B][N][DP]
    const float* __restrict__ W)   // [D][N][DD][DP]
{
    const int d    = blockIdx.x;
    const int tile = blockIdx.y;
    const int n0   = tile * TILE_N;
    const int t    = threadIdx.x;
    const int j    = t & 15;
    const int nl   = t >> 4;
    const int n    = n0 + nl;
    const int lane = t & 31;
    const int w    = t >> 5;

    const float4* wp = reinterpret_cast<const float4*>(
        W + ((size_t)(d * NCAP + n) * DD + j) * DP);
    const float4 w0 = wp[0];
    const float4 w1 = wp[1];

    __shared__ __align__(16) float us[BSZ][TILE_N][DP];   // 8 KB
    __shared__ float red[BSZ][8][DD];                     // 8 KB

    #pragma unroll
    for (int it = 0; it < 2; ++it) {
        const int idx = it * 256 + t;
        const int b   = idx >> 5;
        const int rem = idx & 31;
        const float4 v = reinterpret_cast<const float4*>(
            u + (size_t)b * NCAP * DP + (size_t)n0 * DP)[rem];
        reinterpret_cast<float4*>(&us[b][0][0])[rem] = v;
    }
    __syncthreads();

    #pragma unroll
    for (int b = 0; b < BSZ; ++b) {
        const float4* up = reinterpret_cast<const float4*>(&us[b][nl][0]);
        const float4 u0 = up[0];
        const float4 u1 = up[1];
        const float acc = w0.x * u0.x + w0.y * u0.y + w0.z * u0.z + w0.w * u0.w
                        + w1.x * u1.x + w1.y * u1.y + w1.z * u1.z + w1.w * u1.w;
        g_U[((size_t)(b * DDIG + d) * NCAP + n) * DD + j] = acc;

        const float ps = acc + __shfl_xor_sync(0xffffffffu, acc, 16);
        if (lane < 16) red[b][w][lane] = ps;
    }
    __syncthreads();

    {
        const int b2 = t >> 4;
        const int j2 = t & 15;
        float s = 0.f;
        #pragma unroll
        for (int ww = 0; ww < 8; ++ww) s += red[b2][ww][j2];
        // striped: 18 CTAs per address instead of 72
        atomicAdd(&g_T4[tile & (TSTRIPE - 1)][(b2 * DDIG + d) * DD + j2], s);
    }
}

// -------------------------------------------------------------------------
// K2: streaming softmax weights (high MLP: 40 independent f4 loads/thread).
// Grid (BSZ, K2CH) = 144 CTAs x 128 threads; thread = one n.
// -------------------------------------------------------------------------
__global__ __launch_bounds__(128) void k2_wgt(
    const float* __restrict__ Bp)   // [D][1][N]
{
    const int b  = blockIdx.x;
    const int ch = blockIdx.y;
    const int t  = threadIdx.x;

    __shared__ float Tsm[DDIG][DD];

    // T[b,d,j] = sum of 4 stripes (160 floats; 640 loads over 128 threads)
    for (int idx = t; idx < DDIG * DD; idx += 128) {
        float s = 0.f;
        #pragma unroll
        for (int c = 0; c < TSTRIPE; ++c)
            s += g_T4[c][b * DDIG * DD + idx];
        Tsm[idx >> 4][idx & 15] = s;
    }
    __syncthreads();

    const int n = ch * K2N + t;
    const float inv_sqrt8 = 0.3535533905932738f;

    float a[DDIG];
    #pragma unroll
    for (int d = 0; d < DDIG; ++d) {
        const float4* r = reinterpret_cast<const float4*>(
            g_U + ((size_t)(b * DDIG + d) * NCAP + n) * DD);
        const float4 v0 = r[0], v1 = r[1], v2 = r[2], v3 = r[3];
        const float* T = Tsm[d];
        a[d] = (T[0]  * v0.x + T[1]  * v0.y + T[2]  * v0.z + T[3]  * v0.w
              + T[4]  * v1.x + T[5]  * v1.y + T[6]  * v1.z + T[7]  * v1.w
              + T[8]  * v2.x + T[9]  * v2.y + T[10] * v2.z + T[11] * v2.w
              + T[12] * v3.x + T[13] * v3.y + T[14] * v3.z + T[15] * v3.w)
              * inv_sqrt8;
    }

    float m = a[0];
    #pragma unroll
    for (int d = 1; d < DDIG; ++d) m = fmaxf(m, a[d]);
    float e[DDIG], denom = 0.f;
    #pragma unroll
    for (int d = 0; d < DDIG; ++d) { e[d] = __expf(a[d] - m); denom += e[d]; }
    const float rden = 1.f / denom;

    #pragma unroll
    for (int d = 0; d < DDIG; ++d)
        g_wgt[((size_t)(b * DDIG + d)) * NCAP + n] =
            e[d] * rden + __ldg(&Bp[(size_t)d * NCAP + n]);
}

// -------------------------------------------------------------------------
// K3: S[b,d,j] = sum_n wgt[b,d,n] * U[b,d,n,j]  — fully coalesced.
// Grid (160 bd, K3H) x 256 threads. Warp covers 2 full n-rows (128 B).
// Partials -> g_Sp (no atomics). Last CTA finalizes + squashes + resets T.
// -------------------------------------------------------------------------
__global__ __launch_bounds__(256) void k3_comb(float* __restrict__ out)
{
    const int bd   = blockIdx.x;       // b*DDIG + d
    const int half = blockIdx.y;
    const int t    = threadIdx.x;
    const int j    = t & 15;
    const int ng   = t >> 4;           // 0..15: n-group within iteration
    const int lane = t & 31;
    const int w    = t >> 5;

    const float* Ubd = g_U   + (size_t)bd * NCAP * DD;
    const float* wg  = g_wgt + (size_t)bd * NCAP;
    const int nb     = half * K3N;

    float s = 0.f;
    #pragma unroll 6
    for (int k = 0; k < K3N / 16; ++k) {      // 36 iters
        const int n = nb + k * 16 + ng;
        s += __ldg(&wg[n]) * Ubd[(size_t)n * DD + j];   // warp: 128B contiguous
    }

    // lanes l and l+16 share j: one xor16, then 8-warp smem combine
    s += __shfl_xor_sync(0xffffffffu, s, 16);
    __shared__ float red[8][DD];
    if (lane < 16) red[w][lane] = s;
    __syncthreads();

    if (t < DD) {
        float v = 0.f;
        #pragma unroll
        for (int ww = 0; ww < 8; ++ww) v += red[ww][t];
        g_Sp[half][bd * DD + t] = v;
    }

    // ---- last-CTA finalize ----
    __threadfence();
    __shared__ unsigned int is_last;
    __syncthreads();
    if (t == 0)
        is_last = (atomicInc(&g_cnt, K3CTAS - 1) == K3CTAS - 1) ? 1u : 0u;
    __syncthreads();
    if (!is_last) return;

    __shared__ float Ssm[BSZ * DDIG * DD];    // 10 KB
    __shared__ float coef[BSZ * DDIG];

    for (int idx = t; idx < BSZ * DDIG * DD; idx += 256) {
        float v = 0.f;
        #pragma unroll
        for (int h = 0; h < K3H; ++h)
            v += __ldcg(&g_Sp[h][idx]);       // L2-fresh
        Ssm[idx] = v;
    }
    // reset T stripes for next call (all k2 readers provably done)
    for (int idx = t; idx < TSTRIPE * BSZ * DDIG * DD; idx += 256)
        g_T4[idx / (BSZ * DDIG * DD)][idx % (BSZ * DDIG * DD)] = 0.f;
    __syncthreads();

    if (t < BSZ * DDIG) {                     // t = b*10+d
        float nn = 0.f;
        #pragma unroll
        for (int jj = 0; jj < DD; ++jj) {
            const float v = Ssm[t * DD + jj];
            nn += v * v;
        }
        const float norm = sqrtf(nn);
        const float EPS  = 1e-7f;
        coef[t] = (1.f - 1.f / (__expf(norm) + EPS)) / (norm + EPS);
    }
    __syncthreads();
    for (int idx = t; idx < BSZ * DDIG * DD; idx += 256)
        out[idx] = coef[idx >> 4] * Ssm[idx];
}

// -------------------------------------------------------------------------
extern "C" void kernel_launch(void* const* d_in, const int* in_sizes, int n_in,
                              void* d_out, int out_size)
{
    const float* u  = (const float*)d_in[0];   // primary_caps [16,1152,8]
    const float* W  = (const float*)d_in[1];   // W            [10,1152,16,8]
    const float* Bp = (const float*)d_in[2];   // B_prior      [10,1,1152]
    float* out      = (float*)d_out;           // [16,10,16]

    (void)in_sizes; (void)n_in; (void)out_size;

    k1_votes<<<dim3(DDIG, NT), 256>>>(u, W);
    k2_wgt  <<<dim3(BSZ, K2CH), 128>>>(Bp);
    k3_comb <<<dim3(BSZ * DDIG, K3H), 256>>>(out);
}

// round 13
// speedup vs baseline: 1.5550x; 1.4484x over previous
#include <cuda_runtime.h>
#include <cuda_fp16.h>
#include <math.h>
#include <cstdint>

#define BSZ  16      // batch
#define NCAP 1152    // primary caps
#define DP   8       // dim primary
#define DDIG 10      // digit caps
#define DD   16      // dim digit
#define JP   (DD/2)  // half2 pairs per row = 8

#define TILE_N 16
#define NT (NCAP / TILE_N)   // 72

#define K2CH 9               // k2 chunks per b
#define K2N (NCAP / K2CH)    // 128

// Scratch (device globals; fully overwritten every call)
__device__ __align__(16) __half2 g_Uh[BSZ * DDIG * NCAP * JP];  // U_hat fp16 (5.9 MB)
__device__ __align__(16) float g_Tp[BSZ * DDIG * DD * NT];      // T tile partials (fp32)
__device__ __align__(16) float g_wgt[BSZ * DDIG * NCAP];        // weights [b][d][n]

// -------------------------------------------------------------------------
// K1: votes. thread=(nl 0..15, jp 0..7); computes j-pair for all 16 b,
// stores half2, accumulates fp32 T tile-partials (no atomics).
// Grid (DDIG, NT) = 720 CTAs x 128 threads.
// -------------------------------------------------------------------------
__global__ __launch_bounds__(128) void k1_votes(
    const float* __restrict__ u,   // [B][N][DP]
    const float* __restrict__ W)   // [D][N][DD][DP]
{
    const int d    = blockIdx.x;
    const int tile = blockIdx.y;
    const int n0   = tile * TILE_N;
    const int t    = threadIdx.x;
    const int jp   = t & 7;
    const int nl   = t >> 3;
    const int n    = n0 + nl;
    const int lane = t & 31;
    const int w    = t >> 5;

    // W rows j=2jp, 2jp+1: 64 B contiguous = 4 float4 (issued up front)
    const float4* wp = reinterpret_cast<const float4*>(
        W + ((size_t)(d * NCAP + n) * DD + 2 * jp) * DP);
    const float4 w0 = wp[0];
    const float4 w1 = wp[1];
    const float4 w2 = wp[2];
    const float4 w3 = wp[3];

    __shared__ __align__(16) float us[BSZ][TILE_N][DP];   // 8 KB
    __shared__ float2 red[BSZ][4][JP];                    // 4 KB

    // stage u tile: 512 float4, 4 per thread
    #pragma unroll
    for (int it = 0; it < 4; ++it) {
        const int idx = it * 128 + t;
        const int b   = idx >> 5;
        const int rem = idx & 31;
        const float4 v = reinterpret_cast<const float4*>(
            u + (size_t)b * NCAP * DP + (size_t)n0 * DP)[rem];
        reinterpret_cast<float4*>(&us[b][0][0])[rem] = v;
    }
    __syncthreads();

    #pragma unroll
    for (int b = 0; b < BSZ; ++b) {
        const float4* up = reinterpret_cast<const float4*>(&us[b][nl][0]);
        const float4 u0 = up[0];
        const float4 u1 = up[1];
        const float accE = w0.x * u0.x + w0.y * u0.y + w0.z * u0.z + w0.w * u0.w
                         + w1.x * u1.x + w1.y * u1.y + w1.z * u1.z + w1.w * u1.w;
        const float accO = w2.x * u0.x + w2.y * u0.y + w2.z * u0.z + w2.w * u0.w
                         + w3.x * u1.x + w3.y * u1.y + w3.z * u1.z + w3.w * u1.w;

        // warp stores 128 B contiguous
        g_Uh[((size_t)(b * DDIG + d) * NCAP + n) * JP + jp] =
            __floats2half2_rn(accE, accO);

        // T partial over nl (4 nl per warp): xor8 + xor16
        float pe = accE, po = accO;
        pe += __shfl_xor_sync(0xffffffffu, pe, 8);
        pe += __shfl_xor_sync(0xffffffffu, pe, 16);
        po += __shfl_xor_sync(0xffffffffu, po, 8);
        po += __shfl_xor_sync(0xffffffffu, po, 16);
        if (lane < 8) red[b][w][lane] = make_float2(pe, po);
    }
    __syncthreads();

    // 256 (b,j) outputs over 128 threads: 2 per thread
    #pragma unroll
    for (int k = 0; k < 2; ++k) {
        const int idx = k * 128 + t;      // 0..255
        const int b2  = idx >> 4;
        const int j2  = idx & 15;
        const int jp2 = j2 >> 1;
        float s = 0.f;
        #pragma unroll
        for (int ww = 0; ww < 4; ++ww) {
            const float2 v = red[b2][ww][jp2];
            s += (j2 & 1) ? v.y : v.x;
        }
        g_Tp[((size_t)(b2 * DDIG + d) * DD + j2) * NT + tile] = s;
    }
}

// -------------------------------------------------------------------------
// K2: streaming softmax weights. Grid (BSZ, 9) x 128 threads; thread = one n.
// High MLP: 20 independent LDG.128 over the 10 d rows (half2 data).
// -------------------------------------------------------------------------
__global__ __launch_bounds__(128) void k2_wgt(
    const float* __restrict__ Bp)   // [D][1][N]
{
    const int b  = blockIdx.x;
    const int ch = blockIdx.y;
    const int t  = threadIdx.x;

    __shared__ float Tsm[DDIG][DD];

    // T[b,d,j] from 72 contiguous tile partials (18 f4 per (d,j))
    for (int idx = t; idx < DDIG * DD; idx += 128) {
        const float4* p = reinterpret_cast<const float4*>(
            &g_Tp[(size_t)(b * DDIG * DD + idx) * NT]);
        float s = 0.f;
        #pragma unroll
        for (int k = 0; k < NT / 4; ++k) {
            const float4 v = p[k];
            s += v.x + v.y + v.z + v.w;
        }
        Tsm[idx >> 4][idx & 15] = s;
    }
    __syncthreads();

    const int n = ch * K2N + t;
    const float inv_sqrt8 = 0.3535533905932738f;

    float a[DDIG];
    #pragma unroll
    for (int d = 0; d < DDIG; ++d) {
        const uint4* r = reinterpret_cast<const uint4*>(
            g_Uh + ((size_t)(b * DDIG + d) * NCAP + n) * JP);
        const uint4 A = r[0];
        const uint4 B = r[1];
        const float* T = Tsm[d];
        float s = 0.f;
        {
            const float2 f0 = __half22float2(*reinterpret_cast<const __half2*>(&A.x));
            const float2 f1 = __half22float2(*reinterpret_cast<const __half2*>(&A.y));
            const float2 f2 = __half22float2(*reinterpret_cast<const __half2*>(&A.z));
            const float2 f3 = __half22float2(*reinterpret_cast<const __half2*>(&A.w));
            s += T[0] * f0.x + T[1] * f0.y + T[2] * f1.x + T[3] * f1.y
               + T[4] * f2.x + T[5] * f2.y + T[6] * f3.x + T[7] * f3.y;
        }
        {
            const float2 f0 = __half22float2(*reinterpret_cast<const __half2*>(&B.x));
            const float2 f1 = __half22float2(*reinterpret_cast<const __half2*>(&B.y));
            const float2 f2 = __half22float2(*reinterpret_cast<const __half2*>(&B.z));
            const float2 f3 = __half22float2(*reinterpret_cast<const __half2*>(&B.w));
            s += T[8]  * f0.x + T[9]  * f0.y + T[10] * f1.x + T[11] * f1.y
               + T[12] * f2.x + T[13] * f2.y + T[14] * f3.x + T[15] * f3.y;
        }
        a[d] = s * inv_sqrt8;
    }

    float m = a[0];
    #pragma unroll
    for (int d = 1; d < DDIG; ++d) m = fmaxf(m, a[d]);
    float e[DDIG], denom = 0.f;
    #pragma unroll
    for (int d = 0; d < DDIG; ++d) { e[d] = __expf(a[d] - m); denom += e[d]; }
    const float rden = 1.f / denom;

    #pragma unroll
    for (int d = 0; d < DDIG; ++d)
        g_wgt[((size_t)(b * DDIG + d)) * NCAP + n] =
            e[d] * rden + __ldg(&Bp[(size_t)d * NCAP + n]);
}

// -------------------------------------------------------------------------
// K3: S[b,d,:] = sum_n wgt[b,d,n] * U[b,d,n,:]; inline squash.
// Grid (160) x 512 threads; thread=(jp 0..7, ng 0..63). Coalesced half2.
// No atomics, no fences — each CTA owns its (b,d) end-to-end.
// -------------------------------------------------------------------------
__global__ __launch_bounds__(512) void k3_out(float* __restrict__ out)
{
    const int bd   = blockIdx.x;      // b*DDIG + d
    const int t    = threadIdx.x;
    const int jp   = t & 7;
    const int ng   = t >> 3;          // 0..63
    const int lane = t & 31;
    const int w    = t >> 5;          // 0..15

    __shared__ float wgs[NCAP];       // 4.6 KB
    __shared__ float2 red[16][JP];    // 1 KB
    __shared__ float Ssm[DD];
    __shared__ float coef_sh;

    const float* wg = g_wgt + (size_t)bd * NCAP;
    for (int idx = t; idx < NCAP / 4; idx += 512)
        reinterpret_cast<float4*>(wgs)[idx] =
            reinterpret_cast<const float4*>(wg)[idx];
    __syncthreads();

    const __half2* Ub = g_Uh + (size_t)bd * NCAP * JP;

    float2 acc = make_float2(0.f, 0.f);
    #pragma unroll
    for (int k = 0; k < NCAP / 64; ++k) {     // 18 iters, independent loads
        const int n = k * 64 + ng;
        const float2 f = __half22float2(Ub[(size_t)n * JP + jp]);
        const float wv = wgs[n];
        acc.x += wv * f.x;
        acc.y += wv * f.y;
    }

    // reduce over ng-within-warp (lane>>3): xor8 + xor16
    acc.x += __shfl_xor_sync(0xffffffffu, acc.x, 8);
    acc.x += __shfl_xor_sync(0xffffffffu, acc.x, 16);
    acc.y += __shfl_xor_sync(0xffffffffu, acc.y, 8);
    acc.y += __shfl_xor_sync(0xffffffffu, acc.y, 16);
    if (lane < 8) red[w][lane] = acc;
    __syncthreads();

    if (t < JP) {
        float sx = 0.f, sy = 0.f;
        #pragma unroll
        for (int ww = 0; ww < 16; ++ww) {
            const float2 v = red[ww][t];
            sx += v.x; sy += v.y;
        }
        Ssm[2 * t]     = sx;
        Ssm[2 * t + 1] = sy;
    }
    __syncthreads();
    if (t == 0) {
        float nn = 0.f;
        #pragma unroll
        for (int jj = 0; jj < DD; ++jj) nn += Ssm[jj] * Ssm[jj];
        const float norm = sqrtf(nn);
        const float EPS  = 1e-7f;
        coef_sh = (1.f - 1.f / (__expf(norm) + EPS)) / (norm + EPS);
    }
    __syncthreads();
    if (t < DD)
        out[(size_t)bd * DD + t] = coef_sh * Ssm[t];
}

// -------------------------------------------------------------------------
extern "C" void kernel_launch(void* const* d_in, const int* in_sizes, int n_in,
                              void* d_out, int out_size)
{
    const float* u  = (const float*)d_in[0];   // primary_caps [16,1152,8]
    const float* W  = (const float*)d_in[1];   // W            [10,1152,16,8]
    const float* Bp = (const float*)d_in[2];   // B_prior      [10,1,1152]
    float* out      = (float*)d_out;           // [16,10,16]

    (void)in_sizes; (void)n_in; (void)out_size;

    k1_votes<<<dim3(DDIG, NT), 128>>>(u, W);
    k2_wgt  <<<dim3(BSZ, K2CH), 128>>>(Bp);
    k3_out  <<<BSZ * DDIG, 512>>>(out);
}